// round 5
// baseline (speedup 1.0000x reference)
#include <cuda_runtime.h>
#include <cstdint>
#include <cstddef>

#define BATCH 128
#define TDEC  550
#define TENC  500
#define EDIM  512
#define VOCAB 31
#define NBLK  148
#define NTHR  256

// ---------------- scratch state (device globals; no allocations) ----------------
__device__ __align__(16) float g_keys[(size_t)BATCH * TENC * EDIM];
__device__ __align__(16) float g_values[(size_t)BATCH * TENC * EDIM];
__device__ __align__(16) float g_x0[BATCH * 1536];       // [emb | ctx | h0]
__device__ __align__(16) float g_x1[BATCH * 1024];       // [h0  | h1]
__device__ __align__(16) float g_x2[BATCH * 1024];       // [h1  | ctx]
__device__ __align__(16) float g_gates[BATCH * 2048];
__device__ __align__(16) float g_c0[BATCH * EDIM];
__device__ __align__(16) float g_c1[BATCH * EDIM];
__device__ __align__(16) float g_cdnpart[4][BATCH * EDIM];
__device__ unsigned g_bar_count;
__device__ volatile unsigned g_bar_gen;

__device__ __forceinline__ float4 ld4(const float* p) {
    return *reinterpret_cast<const float4*>(p);
}
__device__ __forceinline__ float sigmoidf_(float x) {
    return 1.0f / (1.0f + expf(-x));
}

// ---------------- grid barrier (all NBLK blocks co-resident) ----------------
__device__ __forceinline__ void gbar() {
    __syncthreads();
    __threadfence();
    if (threadIdx.x == 0) {
        unsigned gen = g_bar_gen;
        if (atomicAdd(&g_bar_count, 1u) == NBLK - 1) {
            g_bar_count = 0;
            __threadfence();
            g_bar_gen = gen + 1;
        } else {
            while (g_bar_gen == gen) { }
        }
    }
    __syncthreads();
}

// ---------------- init ----------------
__global__ void init_kernel(const float* __restrict__ emb) {
    int i = blockIdx.x * 256 + threadIdx.x;
    if (i < BATCH * EDIM) {
        g_c0[i] = 0.f;
        g_c1[i] = 0.f;
        int b = i >> 9, u = i & 511;
        g_x1[b * 1024 + 512 + u] = 0.f;           // h1 = 0
        g_x0[b * 1536 + u] = emb[u];              // emb[SOS=0]
        g_x0[b * 1536 + 512 + u] = 0.f;           // ctx = 0
        g_x0[b * 1536 + 1024 + u] = 0.f;          // h0 = 0
    }
    if (i == 0) { g_bar_count = 0; g_bar_gen = 0; }
}

// ---------------- K/V precompute: C[64000,512] = Enc[64000,512] @ W[512,512] ----------------
__global__ void kv_gemm_kernel(const float* __restrict__ enc,
                               const float* __restrict__ wk,
                               const float* __restrict__ wv) {
    const float* W = (blockIdx.z == 0) ? wk : wv;
    float* C = (blockIdx.z == 0) ? g_keys : g_values;
    int m0 = blockIdx.x * 64;
    int n0 = blockIdx.y * 64;
    __shared__ __align__(16) float As[16][64];
    __shared__ __align__(16) float Ws[16][64];
    int t = threadIdx.x;              // 256
    int tx = t & 15, ty = t >> 4;
    int ar = t >> 2;
    int ak = (t & 3) * 4;
    int wr = t >> 4;
    int wn = (t & 15) * 4;
    float acc[4][4] = {};
    for (int k0 = 0; k0 < 512; k0 += 16) {
        float4 av = ld4(enc + (size_t)(m0 + ar) * 512 + k0 + ak);
        float4 wv4 = ld4(W + (size_t)(k0 + wr) * 512 + n0 + wn);
        __syncthreads();
        As[ak + 0][ar] = av.x; As[ak + 1][ar] = av.y;
        As[ak + 2][ar] = av.z; As[ak + 3][ar] = av.w;
        *reinterpret_cast<float4*>(&Ws[wr][wn]) = wv4;
        __syncthreads();
#pragma unroll
        for (int k = 0; k < 16; k++) {
            float4 a = *reinterpret_cast<const float4*>(&As[k][ty * 4]);
            float4 w = *reinterpret_cast<const float4*>(&Ws[k][tx * 4]);
            acc[0][0] += a.x * w.x; acc[0][1] += a.x * w.y; acc[0][2] += a.x * w.z; acc[0][3] += a.x * w.w;
            acc[1][0] += a.y * w.x; acc[1][1] += a.y * w.y; acc[1][2] += a.y * w.z; acc[1][3] += a.y * w.w;
            acc[2][0] += a.z * w.x; acc[2][1] += a.z * w.y; acc[2][2] += a.z * w.z; acc[2][3] += a.z * w.w;
            acc[3][0] += a.w * w.x; acc[3][1] += a.w * w.y; acc[3][2] += a.w * w.z; acc[3][3] += a.w * w.w;
        }
    }
#pragma unroll
    for (int r = 0; r < 4; r++) {
        float4 o = make_float4(acc[r][0], acc[r][1], acc[r][2], acc[r][3]);
        *reinterpret_cast<float4*>(C + (size_t)(m0 + ty * 4 + r) * 512 + n0 + tx * 4) = o;
    }
}

// ---------------- in-persistent GEMM tile: 16 units x 128 batch ----------------
// out[b, n0+u] (+=nothing, direct) = sum_{k in [k_begin,k_end)} x[b,k] * Wrow(n0+u)[k]
// Wrow n: k < Ka -> Wa[n*Ka + k], else Wb[n*Kb + (k-Ka)]
__device__ __forceinline__ void gemm_tile(
    const float* __restrict__ x, int ldx,
    const float* __restrict__ Wa, int Ka,
    const float* __restrict__ Wb, int Kb,
    int n0, int k_begin, int k_end,
    float* __restrict__ out, int ldo,
    float* __restrict__ As,   // 2048 floats [16][128]
    float* __restrict__ Ws)   // 256 floats  [16][16]
{
    int t = threadIdx.x;
    int w = t >> 5, l = t & 31;
    int bg = l >> 3;                   // 0..3
    int ul = (l & 7) * 2;              // unit pair within tile
    int bbase = w * 16 + bg * 4;       // batch base for this thread
    int ab = t >> 1;                   // loader: batch row 0..127
    int akp = (t & 1) * 8;             // loader: k sub-offset
    int wu = t >> 4;                   // Ws loader: unit 0..15
    int wkk = t & 15;                  // Ws loader: k 0..15
    float acc[4][2] = {};
    for (int k0 = k_begin; k0 < k_end; k0 += 16) {
        float4 v0 = ld4(x + (size_t)ab * ldx + k0 + akp);
        float4 v1 = ld4(x + (size_t)ab * ldx + k0 + akp + 4);
        int k = k0 + wkk;
        float wval = (k < Ka) ? Wa[(size_t)(n0 + wu) * Ka + k]
                              : Wb[(size_t)(n0 + wu) * Kb + (k - Ka)];
        __syncthreads();
        As[(akp + 0) * 128 + ab] = v0.x; As[(akp + 1) * 128 + ab] = v0.y;
        As[(akp + 2) * 128 + ab] = v0.z; As[(akp + 3) * 128 + ab] = v0.w;
        As[(akp + 4) * 128 + ab] = v1.x; As[(akp + 5) * 128 + ab] = v1.y;
        As[(akp + 6) * 128 + ab] = v1.z; As[(akp + 7) * 128 + ab] = v1.w;
        Ws[wkk * 16 + wu] = wval;
        __syncthreads();
#pragma unroll
        for (int kk = 0; kk < 16; kk++) {
            float4 a = *reinterpret_cast<const float4*>(&As[kk * 128 + bbase]);
            float2 wv = *reinterpret_cast<const float2*>(&Ws[kk * 16 + ul]);
            acc[0][0] += a.x * wv.x; acc[0][1] += a.x * wv.y;
            acc[1][0] += a.y * wv.x; acc[1][1] += a.y * wv.y;
            acc[2][0] += a.z * wv.x; acc[2][1] += a.z * wv.y;
            acc[3][0] += a.w * wv.x; acc[3][1] += a.w * wv.y;
        }
    }
#pragma unroll
    for (int r = 0; r < 4; r++) {
        *reinterpret_cast<float2*>(&out[(size_t)(bbase + r) * ldo + n0 + ul]) =
            make_float2(acc[r][0], acc[r][1]);
    }
}

// ---------------- LSTM activation phase (elementwise) ----------------
__device__ __forceinline__ void lstm_act(
    const float* __restrict__ b_ih, const float* __restrict__ b_hh,
    float* __restrict__ c_st,
    float* __restrict__ hdst0, int ld0, int off0,   // first h destination
    float* __restrict__ hdst1, int ld1, int off1)   // second h destination
{
    int start = blockIdx.x * NTHR + threadIdx.x;
    for (int i = start; i < BATCH * EDIM; i += NBLK * NTHR) {
        int b = i >> 9, u = i & 511;
        const float* g = g_gates + (size_t)b * 2048;
        float gi = g[u]            + b_ih[u]            + b_hh[u];
        float gf = g[512 + u]      + b_ih[512 + u]      + b_hh[512 + u];
        float gg = g[1024 + u]     + b_ih[1024 + u]     + b_hh[1024 + u];
        float go = g[1536 + u]     + b_ih[1536 + u]     + b_hh[1536 + u];
        float cn = sigmoidf_(gf) * c_st[i] + sigmoidf_(gi) * tanhf(gg);
        c_st[i] = cn;
        float h = sigmoidf_(go) * tanhf(cn);
        hdst0[(size_t)b * ld0 + off0 + u] = h;
        hdst1[(size_t)b * ld1 + off1 + u] = h;
    }
}

// ---------------- persistent decoder ----------------
__global__ void __launch_bounds__(NTHR, 1) decoder_kernel(
    const float* __restrict__ emb,
    const float* __restrict__ w_ih0, const float* __restrict__ w_hh0,
    const float* __restrict__ b_ih0, const float* __restrict__ b_hh0,
    const float* __restrict__ w_ih1, const float* __restrict__ w_hh1,
    const float* __restrict__ b_ih1, const float* __restrict__ b_hh1,
    const float* __restrict__ w_o2c, const float* __restrict__ b_o2c,
    const float* __restrict__ b_cp,
    float* __restrict__ out_logits, float* __restrict__ out_attn)
{
    __shared__ __align__(16) float smpool[2368];
    int blk = blockIdx.x;
    int t = threadIdx.x;
    int w = t >> 5, l = t & 31;

    for (int s = 0; s < TDEC; s++) {
        // ---- LSTM0 GEMM: gates = x0 @ [w_ih0|w_hh0]^T ----
        if (blk < 128)
            gemm_tile(g_x0, 1536, w_ih0, 1024, w_hh0, 512,
                      blk * 16, 0, 1536, g_gates, 2048, smpool, smpool + 2048);
        gbar();

        // ---- LSTM0 activations: h0 -> x0[h0 slot], x1[0:512) ----
        lstm_act(b_ih0, b_hh0, g_c0, g_x0, 1536, 1024, g_x1, 1024, 0);
        gbar();

        // ---- LSTM1 GEMM ----
        if (blk < 128)
            gemm_tile(g_x1, 1024, w_ih1, 512, w_hh1, 512,
                      blk * 16, 0, 1024, g_gates, 2048, smpool, smpool + 2048);
        gbar();

        // ---- LSTM1 activations: h1 -> x1[512:1024), x2[0:512) ----
        lstm_act(b_ih1, b_hh1, g_c1, g_x1, 1024, 512, g_x2, 1024, 0);
        gbar();

        // ---- attention: energy + softmax + ctx ----
        if (blk < 128) {
            int b = blk;
            float* h1s   = smpool;          // 512
            float* es    = smpool + 512;    // 512
            float* red   = smpool + 1024;   // 40
            float* parts = smpool + 1088;   // 1024
            const float* xb = g_x2 + (size_t)b * 1024;
            h1s[t] = xb[t]; h1s[t + 256] = xb[t + 256];
            __syncthreads();
            const float* kb = g_keys + (size_t)b * TENC * EDIM;
            for (int tt = w * 2; tt < TENC; tt += 16) {
                const float* k0p = kb + (size_t)tt * 512;
                const float* k1p = k0p + 512;
                float s0 = 0.f, s1 = 0.f;
#pragma unroll
                for (int j = 0; j < 4; j++) {
                    int off = l * 4 + j * 128;
                    float4 a = ld4(k0p + off);
                    float4 c = ld4(k1p + off);
                    float4 h = *reinterpret_cast<const float4*>(&h1s[off]);
                    s0 += a.x * h.x + a.y * h.y + a.z * h.z + a.w * h.w;
                    s1 += c.x * h.x + c.y * h.y + c.z * h.z + c.w * h.w;
                }
#pragma unroll
                for (int o = 16; o > 0; o >>= 1) {
                    s0 += __shfl_xor_sync(0xffffffffu, s0, o);
                    s1 += __shfl_xor_sync(0xffffffffu, s1, o);
                }
                if (l == 0) { es[tt] = s0; es[tt + 1] = s1; }
            }
            __syncthreads();
            float m = -3.4e38f;
            for (int tt = t; tt < TENC; tt += 256) m = fmaxf(m, es[tt]);
#pragma unroll
            for (int o = 16; o > 0; o >>= 1) m = fmaxf(m, __shfl_xor_sync(0xffffffffu, m, o));
            if (l == 0) red[w] = m;
            __syncthreads();
            if (t == 0) {
                float mm = red[0];
                for (int i = 1; i < 8; i++) mm = fmaxf(mm, red[i]);
                red[8] = mm;
            }
            __syncthreads();
            float mx = red[8];
            float ssum = 0.f;
            for (int tt = t; tt < TENC; tt += 256) {
                float p = expf(es[tt] - mx);
                es[tt] = p;
                ssum += p;
            }
#pragma unroll
            for (int o = 16; o > 0; o >>= 1) ssum += __shfl_xor_sync(0xffffffffu, ssum, o);
            if (l == 0) red[w] = ssum;
            __syncthreads();
            if (t == 0) {
                float ss = 0.f;
                for (int i = 0; i < 8; i++) ss += red[i];
                red[8] = ss;
            }
            __syncthreads();
            float inv = 1.f / red[8];
            float* ao = out_attn + ((size_t)b * TDEC + s) * TENC;
            for (int tt = t; tt < TENC; tt += 256) {
                float aw = es[tt] * inv;
                es[tt] = aw;
                ao[tt] = aw;
            }
            __syncthreads();
            // ctx = sum_t aw[t] * values[b,t,:]
            int col = (t & 127) * 4;
            int half = t >> 7;
            const float* vb = g_values + (size_t)b * TENC * EDIM + col;
            float4 acc = make_float4(0.f, 0.f, 0.f, 0.f);
            int tt0 = half * 250;
#pragma unroll 10
            for (int q = 0; q < 250; q++) {
                int tt = tt0 + q;
                float wg = es[tt];
                float4 v = ld4(vb + (size_t)tt * 512);
                acc.x += wg * v.x; acc.y += wg * v.y;
                acc.z += wg * v.z; acc.w += wg * v.w;
            }
            *reinterpret_cast<float4*>(&parts[half * 512 + col]) = acc;
            __syncthreads();
            if (t < 128) {
                int c2 = t * 4;
                float4 p0 = *reinterpret_cast<const float4*>(&parts[c2]);
                float4 p1 = *reinterpret_cast<const float4*>(&parts[512 + c2]);
                float4 cx = make_float4(p0.x + p1.x, p0.y + p1.y, p0.z + p1.z, p0.w + p1.w);
                *reinterpret_cast<float4*>(&g_x0[(size_t)b * 1536 + 512 + c2]) = cx;
                *reinterpret_cast<float4*>(&g_x2[(size_t)b * 1024 + 512 + c2]) = cx;
            }
        }
        gbar();

        // ---- cdn partial GEMM (4-way K split) ----
        if (blk < 128) {
            int q = blk >> 5;
            gemm_tile(g_x2, 1024, w_o2c, 1024, w_o2c, 1024,
                      (blk & 31) * 16, q * 256, q * 256 + 256,
                      g_cdnpart[q], 512, smpool, smpool + 2048);
        }
        gbar();

        // ---- logits + argmax + emb feedback ----
        if (blk < 128) {
            int b = blk;
            float* hs = smpool;                 // 512
            float* wbest = smpool + 512;        // 8
            int* wvid = (int*)(smpool + 520);   // 8
            int* bidx = (int*)(smpool + 528);
            for (int u = t; u < 512; u += 256) {
                float v = b_o2c[u]
                        + g_cdnpart[0][(size_t)b * 512 + u]
                        + g_cdnpart[1][(size_t)b * 512 + u]
                        + g_cdnpart[2][(size_t)b * 512 + u]
                        + g_cdnpart[3][(size_t)b * 512 + u];
                hs[u] = fmaxf(v, 0.f);
            }
            __syncthreads();
            float h[16];
#pragma unroll
            for (int jj = 0; jj < 16; jj++) h[jj] = hs[l + jj * 32];
            float best = -3.4e38f;
            int bv = 0;
            float* lo = out_logits + ((size_t)b * TDEC + s) * VOCAB;
            for (int v = w; v < VOCAB; v += 8) {
                float sv = 0.f;
#pragma unroll
                for (int jj = 0; jj < 16; jj++) sv += h[jj] * emb[(size_t)v * 512 + l + jj * 32];
#pragma unroll
                for (int o = 16; o > 0; o >>= 1) sv += __shfl_xor_sync(0xffffffffu, sv, o);
                if (l == 0) {
                    sv += b_cp[v];
                    lo[v] = sv;
                    if (sv > best) { best = sv; bv = v; }
                }
            }
            if (l == 0) { wbest[w] = best; wvid[w] = bv; }
            __syncthreads();
            if (t == 0) {
                float bb = wbest[0]; int bi = wvid[0];
                for (int i = 1; i < 8; i++) {
                    if (wbest[i] > bb || (wbest[i] == bb && wvid[i] < bi)) {
                        bb = wbest[i]; bi = wvid[i];
                    }
                }
                *bidx = bi;
            }
            __syncthreads();
            int sym = *bidx;
            for (int u = t; u < 512; u += 256)
                g_x0[(size_t)b * 1536 + u] = emb[(size_t)sym * 512 + u];
        }
        gbar();
    }
}

// ---------------- launch ----------------
extern "C" void kernel_launch(void* const* d_in, const int* in_sizes, int n_in,
                              void* d_out, int out_size) {
    const float* enc    = (const float*)d_in[0];
    const float* emb    = (const float*)d_in[1];
    const float* w_ih0  = (const float*)d_in[2];
    const float* w_hh0  = (const float*)d_in[3];
    const float* b_ih0  = (const float*)d_in[4];
    const float* b_hh0  = (const float*)d_in[5];
    const float* w_ih1  = (const float*)d_in[6];
    const float* w_hh1  = (const float*)d_in[7];
    const float* b_ih1  = (const float*)d_in[8];
    const float* b_hh1  = (const float*)d_in[9];
    const float* wk     = (const float*)d_in[10];
    const float* wv     = (const float*)d_in[11];
    const float* w_o2c  = (const float*)d_in[12];
    const float* b_o2c  = (const float*)d_in[13];
    const float* b_cp   = (const float*)d_in[14];
    float* out = (float*)d_out;
    float* out_logits = out;
    float* out_attn = out + (size_t)BATCH * TDEC * VOCAB;

    init_kernel<<<256, 256>>>(emb);
    kv_gemm_kernel<<<dim3(1000, 8, 2), 256>>>(enc, wk, wv);
    decoder_kernel<<<NBLK, NTHR>>>(emb,
                                   w_ih0, w_hh0, b_ih0, b_hh0,
                                   w_ih1, w_hh1, b_ih1, b_hh1,
                                   w_o2c, b_o2c, b_cp,
                                   out_logits, out_attn);
}

// round 7
// speedup vs baseline: 1.0938x; 1.0938x over previous
#include <cuda_runtime.h>
#include <cstdint>
#include <cstddef>

#define BATCH 128
#define TDEC  550
#define TENC  500
#define EDIM  512
#define VOCAB 31
#define NBLK  148
#define NTHR  256

#define FMA2(d, a, b) asm("fma.rn.f32x2 %0, %1, %2, %0;" : "+l"(d) : "l"(a), "l"(b))

// ---------------- scratch state (device globals; no allocations) ----------------
__device__ __align__(16) float g_keys[(size_t)BATCH * TENC * EDIM];
__device__ __align__(16) float g_values[(size_t)BATCH * TENC * EDIM];
__device__ __align__(16) float g_xec[BATCH * 1024];        // [emb | ctx]
__device__ __align__(16) float g_h0buf[2][BATCH * EDIM];
__device__ __align__(16) float g_h1buf[2][BATCH * EDIM];
__device__ __align__(16) float g_ctxbuf[BATCH * EDIM];
__device__ __align__(16) float g_c0[BATCH * EDIM];
__device__ __align__(16) float g_c1[BATCH * EDIM];
__device__ __align__(16) float g_hid[BATCH * EDIM];
__device__ unsigned g_bar_count;
__device__ volatile unsigned g_bar_gen;

__device__ __forceinline__ float4 ld4(const float* p) {
    return *reinterpret_cast<const float4*>(p);
}
__device__ __forceinline__ float sigmoidf_(float x) {
    return 1.0f / (1.0f + expf(-x));
}

// ---------------- grid barrier (all NBLK blocks co-resident) ----------------
__device__ __forceinline__ void gbar() {
    __syncthreads();
    __threadfence();
    if (threadIdx.x == 0) {
        unsigned gen = g_bar_gen;
        if (atomicAdd(&g_bar_count, 1u) == NBLK - 1) {
            g_bar_count = 0;
            __threadfence();
            g_bar_gen = gen + 1;
        } else {
            while (g_bar_gen == gen) { }
        }
    }
    __syncthreads();
}

// ---------------- init ----------------
__global__ void init_kernel(const float* __restrict__ emb) {
    int i = blockIdx.x * 256 + threadIdx.x;
    if (i < BATCH * EDIM) {
        g_c0[i] = 0.f;
        g_c1[i] = 0.f;
        g_h0buf[0][i] = 0.f;
        g_h1buf[0][i] = 0.f;
        int b = i >> 9, u = i & 511;
        g_xec[b * 1024 + u] = emb[u];        // emb[SOS=0]
        g_xec[b * 1024 + 512 + u] = 0.f;     // ctx = 0
    }
    if (i == 0) { g_bar_count = 0; g_bar_gen = 0; }
}

// ---------------- K/V precompute with f32x2 FMA ----------------
__global__ void kv_gemm_kernel(const float* __restrict__ enc,
                               const float* __restrict__ wk,
                               const float* __restrict__ wv) {
    const float* W = (blockIdx.z == 0) ? wk : wv;
    float* C = (blockIdx.z == 0) ? g_keys : g_values;
    int m0 = blockIdx.x * 64;
    int n0 = blockIdx.y * 64;
    __shared__ __align__(16) float As2[1024];   // [k2=8][m=64][2]
    __shared__ __align__(16) float Ws2[1024];   // [k2=8][n=64][2]
    int t = threadIdx.x;              // 256
    int tx = t & 15, ty = t >> 4;
    int ar = t >> 2;
    int ak = (t & 3) * 4;             // even
    int wr = t >> 4;                  // k row 0..15
    int wn = (t & 15) * 4;
    unsigned long long acc[4][4] = {};
    for (int k0 = 0; k0 < 512; k0 += 16) {
        float4 av  = ld4(enc + (size_t)(m0 + ar) * 512 + k0 + ak);
        float4 wv4 = ld4(W + (size_t)(k0 + wr) * 512 + n0 + wn);
        __syncthreads();
        int ah = (ak >> 1) * 128 + ar * 2;
        As2[ah + 0]   = av.x;
        As2[ah + 1]   = av.y;
        As2[ah + 128] = av.z;
        As2[ah + 129] = av.w;
        int wh = (wr >> 1) * 128 + (wr & 1);
        Ws2[wh + (wn + 0) * 2] = wv4.x;
        Ws2[wh + (wn + 1) * 2] = wv4.y;
        Ws2[wh + (wn + 2) * 2] = wv4.z;
        Ws2[wh + (wn + 3) * 2] = wv4.w;
        __syncthreads();
#pragma unroll
        for (int k2 = 0; k2 < 8; k2++) {
            ulonglong2 a01 = *reinterpret_cast<const ulonglong2*>(As2 + k2 * 128 + ty * 8);
            ulonglong2 a23 = *reinterpret_cast<const ulonglong2*>(As2 + k2 * 128 + ty * 8 + 4);
            ulonglong2 w01 = *reinterpret_cast<const ulonglong2*>(Ws2 + k2 * 128 + tx * 8);
            ulonglong2 w23 = *reinterpret_cast<const ulonglong2*>(Ws2 + k2 * 128 + tx * 8 + 4);
            FMA2(acc[0][0], a01.x, w01.x); FMA2(acc[0][1], a01.x, w01.y);
            FMA2(acc[0][2], a01.x, w23.x); FMA2(acc[0][3], a01.x, w23.y);
            FMA2(acc[1][0], a01.y, w01.x); FMA2(acc[1][1], a01.y, w01.y);
            FMA2(acc[1][2], a01.y, w23.x); FMA2(acc[1][3], a01.y, w23.y);
            FMA2(acc[2][0], a23.x, w01.x); FMA2(acc[2][1], a23.x, w01.y);
            FMA2(acc[2][2], a23.x, w23.x); FMA2(acc[2][3], a23.x, w23.y);
            FMA2(acc[3][0], a23.y, w01.x); FMA2(acc[3][1], a23.y, w01.y);
            FMA2(acc[3][2], a23.y, w23.x); FMA2(acc[3][3], a23.y, w23.y);
        }
    }
#pragma unroll
    for (int r = 0; r < 4; r++) {
        float4 o;
        float2 p0 = *reinterpret_cast<float2*>(&acc[r][0]);
        float2 p1 = *reinterpret_cast<float2*>(&acc[r][1]);
        float2 p2 = *reinterpret_cast<float2*>(&acc[r][2]);
        float2 p3 = *reinterpret_cast<float2*>(&acc[r][3]);
        o.x = p0.x + p0.y; o.y = p1.x + p1.y; o.z = p2.x + p2.y; o.w = p3.x + p3.y;
        *reinterpret_cast<float4*>(C + (size_t)(m0 + ty * 4 + r) * 512 + n0 + tx * 4) = o;
    }
}

// ---------------- chunk loader (32-k chunks, pair-interleaved As2) ----------------
__device__ __forceinline__ void load_chunkA(const float* __restrict__ segA, int ldA, int lenA,
                                            const float* __restrict__ segB, int ldB,
                                            int k0, int ab, int koff, float4* r) {
#pragma unroll
    for (int j = 0; j < 4; j++) {
        int k = k0 + koff + j * 4;
        const float* src = (k < lenA) ? segA + (size_t)ab * ldA + k
                                      : segB + (size_t)ab * ldB + (k - lenA);
        r[j] = __ldcg(reinterpret_cast<const float4*>(src));
    }
}

__device__ __forceinline__ void store_chunkA(float* __restrict__ As2, int ab, int koff,
                                             const float4* r) {
#pragma unroll
    for (int j = 0; j < 4; j++) {
        int kl = koff + j * 4;       // local k, even
        int base = (kl >> 1) * 256 + ab * 2;
        As2[base + 0]   = r[j].x;
        As2[base + 1]   = r[j].y;
        As2[base + 256] = r[j].z;
        As2[base + 257] = r[j].w;
    }
}

// ---------------- 16-row GEMM (f32x2), results staged to Gs[16][128] ----------------
template <int K, int LENA>
__device__ __forceinline__ void gemm16(
    const float* __restrict__ segA, int ldA,
    const float* __restrict__ segB, int ldB,
    const float* __restrict__ Wp,   // smem [k/2][16][2]
    float* __restrict__ As2,        // smem 2*4096 floats
    float* __restrict__ Gs)         // smem [16][128] (aliases As2)
{
    int t = threadIdx.x;
    int w = t >> 5, l = t & 31;
    int bbase = w * 16 + (l >> 3) * 4;
    int ul = (l & 7) * 2;
    int bbase2 = bbase * 2, ul2 = ul * 2;
    int ab = t >> 1, koff = (t & 1) * 16;
    constexpr int NCH = K / 32;
    unsigned long long acc[4][2] = {};
    float4 r[4];
    load_chunkA(segA, ldA, LENA, segB, ldB, 0, ab, koff, r);
    int buf = 0;
    for (int c = 0; c < NCH; c++) {
        __syncthreads();
        store_chunkA(As2 + buf * 4096, ab, koff, r);
        if (c + 1 < NCH)
            load_chunkA(segA, ldA, LENA, segB, ldB, (c + 1) * 32, ab, koff, r);
        __syncthreads();
        const float* A = As2 + buf * 4096;
        const float* Wb = Wp + (c * 16) * 32;
#pragma unroll
        for (int k2 = 0; k2 < 16; k2++) {
            ulonglong2 a01 = *reinterpret_cast<const ulonglong2*>(A + k2 * 256 + bbase2);
            ulonglong2 a23 = *reinterpret_cast<const ulonglong2*>(A + k2 * 256 + bbase2 + 4);
            ulonglong2 wvp = *reinterpret_cast<const ulonglong2*>(Wb + k2 * 32 + ul2);
            FMA2(acc[0][0], a01.x, wvp.x); FMA2(acc[0][1], a01.x, wvp.y);
            FMA2(acc[1][0], a01.y, wvp.x); FMA2(acc[1][1], a01.y, wvp.y);
            FMA2(acc[2][0], a23.x, wvp.x); FMA2(acc[2][1], a23.x, wvp.y);
            FMA2(acc[3][0], a23.y, wvp.x); FMA2(acc[3][1], a23.y, wvp.y);
        }
        buf ^= 1;
    }
    __syncthreads();
#pragma unroll
    for (int cc = 0; cc < 2; cc++)
#pragma unroll
        for (int rr = 0; rr < 4; rr++) {
            float2 p = *reinterpret_cast<float2*>(&acc[rr][cc]);
            Gs[(ul + cc) * 128 + bbase + rr] = p.x + p.y;
        }
    __syncthreads();
}

// ---------------- LSTM epilogue: gates -> c,h ----------------
__device__ __forceinline__ void lstm_ep(const float* __restrict__ Gs,
                                        const float* __restrict__ b_ih,
                                        const float* __restrict__ b_hh,
                                        float* __restrict__ cbuf,
                                        float* __restrict__ hbuf, int u0) {
    int t = threadIdx.x;
#pragma unroll
    for (int pp = 0; pp < 2; pp++) {
        int p = t + pp * 256;
        int b = p >> 2, uu = p & 3;
        int u = u0 + uu;
        float gi = Gs[(0  + uu) * 128 + b] + b_ih[u]        + b_hh[u];
        float gf = Gs[(4  + uu) * 128 + b] + b_ih[512 + u]  + b_hh[512 + u];
        float gg = Gs[(8  + uu) * 128 + b] + b_ih[1024 + u] + b_hh[1024 + u];
        float go = Gs[(12 + uu) * 128 + b] + b_ih[1536 + u] + b_hh[1536 + u];
        float cn = sigmoidf_(gf) * cbuf[b * 512 + u] + sigmoidf_(gi) * tanhf(gg);
        cbuf[b * 512 + u] = cn;
        hbuf[b * 512 + u] = sigmoidf_(go) * tanhf(cn);
    }
}

// ---------------- cdn GEMM (4 rows per block, f32x2) ----------------
__device__ __forceinline__ void gemm4_cdn(const float* __restrict__ segA,
                                          const float* __restrict__ segB,
                                          const float* __restrict__ Wc,  // smem [512][4][2]
                                          float* __restrict__ As2,
                                          const float* __restrict__ b_o2c, int u0) {
    int t = threadIdx.x;
    int ab = t >> 1, koff = (t & 1) * 16;
    int b = t & 127, up = (t >> 7) * 2;
    unsigned long long acc[2] = {};
    float4 r[4];
    load_chunkA(segA, 512, 512, segB, 512, 0, ab, koff, r);
    int buf = 0;
    for (int c = 0; c < 32; c++) {
        __syncthreads();
        store_chunkA(As2 + buf * 4096, ab, koff, r);
        if (c + 1 < 32)
            load_chunkA(segA, 512, 512, segB, 512, (c + 1) * 32, ab, koff, r);
        __syncthreads();
        const float* A = As2 + buf * 4096;
        const float* Wb = Wc + (c * 16) * 8;
#pragma unroll
        for (int k2 = 0; k2 < 16; k2++) {
            unsigned long long a =
                *reinterpret_cast<const unsigned long long*>(A + k2 * 256 + b * 2);
            ulonglong2 wvp = *reinterpret_cast<const ulonglong2*>(Wb + k2 * 8 + up * 2);
            FMA2(acc[0], a, wvp.x);
            FMA2(acc[1], a, wvp.y);
        }
        buf ^= 1;
    }
#pragma unroll
    for (int j = 0; j < 2; j++) {
        float2 p = *reinterpret_cast<float2*>(&acc[j]);
        int u = u0 + up + j;
        g_hid[(size_t)b * 512 + u] = fmaxf(p.x + p.y + b_o2c[u], 0.f);
    }
    __syncthreads();
}

// ---------------- persistent decoder ----------------
// dynamic smem layout (floats):
//   W0  @ 0      : 24576  (LSTM0 [768][16][2])
//   W1  @ 24576  : 16384  (LSTM1 [512][16][2])
//   Wc  @ 40960  : 4096   (cdn   [512][4][2])
//   AS  @ 45056  : 8192   (double-buffered chunks / Gs / attention scratch)
#define SMEM_FLOATS 53248
#define SMEM_BYTES  (SMEM_FLOATS * 4)

__global__ void __launch_bounds__(NTHR, 1) decoder_kernel(
    const float* __restrict__ emb,
    const float* __restrict__ w_ih0, const float* __restrict__ w_hh0,
    const float* __restrict__ b_ih0, const float* __restrict__ b_hh0,
    const float* __restrict__ w_ih1, const float* __restrict__ w_hh1,
    const float* __restrict__ b_ih1, const float* __restrict__ b_hh1,
    const float* __restrict__ w_o2c, const float* __restrict__ b_o2c,
    const float* __restrict__ b_cp,
    float* __restrict__ out_logits, float* __restrict__ out_attn)
{
    extern __shared__ __align__(16) float sm[];
    float* W0 = sm;
    float* W1 = sm + 24576;
    float* Wc = sm + 40960;
    float* AS = sm + 45056;
    int blk = blockIdx.x;
    int t = threadIdx.x;
    int w = t >> 5, l = t & 31;
    int u0 = blk * 4;

    // ---- one-time: load weight tiles into smem ----
    if (blk < 128) {
        for (int idx = t; idx < 16 * 1536; idx += NTHR) {
            int rrow = idx / 1536;
            int k = idx - rrow * 1536;
            int gate = rrow >> 2, uu = rrow & 3;
            int gr = gate * 512 + u0 + uu;
            float v = (k < 1024) ? w_ih0[(size_t)gr * 1024 + k]
                                 : w_hh0[(size_t)gr * 512 + (k - 1024)];
            W0[(k >> 1) * 32 + rrow * 2 + (k & 1)] = v;
        }
        for (int idx = t; idx < 16 * 1024; idx += NTHR) {
            int rrow = idx >> 10;
            int k = idx & 1023;
            int gate = rrow >> 2, uu = rrow & 3;
            int gr = gate * 512 + u0 + uu;
            float v = (k < 512) ? w_ih1[(size_t)gr * 512 + k]
                                : w_hh1[(size_t)gr * 512 + (k - 512)];
            W1[(k >> 1) * 32 + rrow * 2 + (k & 1)] = v;
        }
        for (int idx = t; idx < 4 * 1024; idx += NTHR) {
            int uu = idx >> 10;
            int k = idx & 1023;
            float v = w_o2c[(size_t)(u0 + uu) * 1024 + k];
            Wc[(k >> 1) * 8 + uu * 2 + (k & 1)] = v;
        }
    }
    __syncthreads();

    for (int s = 0; s < TDEC; s++) {
        int par = s & 1;

        // ---- LSTM0 ----
        if (blk < 128) {
            gemm16<1536, 1024>(g_xec, 1024, g_h0buf[par], 512, W0, AS, AS);
            lstm_ep(AS, b_ih0, b_hh0, g_c0, g_h0buf[par ^ 1], u0);
        }
        gbar();

        // ---- LSTM1 ----
        if (blk < 128) {
            gemm16<1024, 512>(g_h0buf[par ^ 1], 512, g_h1buf[par], 512, W1, AS, AS);
            lstm_ep(AS, b_ih1, b_hh1, g_c1, g_h1buf[par ^ 1], u0);
        }
        gbar();

        // ---- attention ----
        if (blk < 128) {
            int b = blk;
            float* h1s   = AS;           // 512
            float* es    = AS + 512;     // 512
            float* red   = AS + 1024;    // 48
            float* parts = AS + 1088;    // 1024
            const float* h1 = g_h1buf[par ^ 1];
            h1s[t]       = __ldcg(&h1[b * 512 + t]);
            h1s[t + 256] = __ldcg(&h1[b * 512 + t + 256]);
            __syncthreads();
            const float* kb = g_keys + (size_t)b * TENC * EDIM;
            for (int tt = w * 2; tt < TENC; tt += 16) {
                const float* k0p = kb + (size_t)tt * 512;
                const float* k1p = k0p + 512;
                float s0 = 0.f, s1 = 0.f;
#pragma unroll
                for (int j = 0; j < 4; j++) {
                    int off = l * 4 + j * 128;
                    float4 a = ld4(k0p + off);
                    float4 c = ld4(k1p + off);
                    float4 h = *reinterpret_cast<const float4*>(&h1s[off]);
                    s0 += a.x * h.x + a.y * h.y + a.z * h.z + a.w * h.w;
                    s1 += c.x * h.x + c.y * h.y + c.z * h.z + c.w * h.w;
                }
#pragma unroll
                for (int o = 16; o > 0; o >>= 1) {
                    s0 += __shfl_xor_sync(0xffffffffu, s0, o);
                    s1 += __shfl_xor_sync(0xffffffffu, s1, o);
                }
                if (l == 0) { es[tt] = s0; es[tt + 1] = s1; }
            }
            __syncthreads();
            float m = -3.4e38f;
            for (int tt = t; tt < TENC; tt += 256) m = fmaxf(m, es[tt]);
#pragma unroll
            for (int o = 16; o > 0; o >>= 1) m = fmaxf(m, __shfl_xor_sync(0xffffffffu, m, o));
            if (l == 0) red[w] = m;
            __syncthreads();
            if (t == 0) {
                float mm = red[0];
                for (int i = 1; i < 8; i++) mm = fmaxf(mm, red[i]);
                red[8] = mm;
            }
            __syncthreads();
            float mx = red[8];
            float ssum = 0.f;
            for (int tt = t; tt < TENC; tt += 256) {
                float p = expf(es[tt] - mx);
                es[tt] = p;
                ssum += p;
            }
#pragma unroll
            for (int o = 16; o > 0; o >>= 1) ssum += __shfl_xor_sync(0xffffffffu, ssum, o);
            if (l == 0) red[w] = ssum;
            __syncthreads();
            if (t == 0) {
                float ss = 0.f;
                for (int i = 0; i < 8; i++) ss += red[i];
                red[8] = ss;
            }
            __syncthreads();
            float inv = 1.f / red[8];
            float* ao = out_attn + ((size_t)b * TDEC + s) * TENC;
            for (int tt = t; tt < TENC; tt += 256) {
                float aw = es[tt] * inv;
                es[tt] = aw;
                ao[tt] = aw;
            }
            __syncthreads();
            int col = (t & 127) * 4;
            int half = t >> 7;
            const float* vb = g_values + (size_t)b * TENC * EDIM + col;
            float4 acc = make_float4(0.f, 0.f, 0.f, 0.f);
            int tt0 = half * 250;
#pragma unroll 10
            for (int q = 0; q < 250; q++) {
                int tt = tt0 + q;
                float wg = es[tt];
                float4 v = ld4(vb + (size_t)tt * 512);
                acc.x += wg * v.x; acc.y += wg * v.y;
                acc.z += wg * v.z; acc.w += wg * v.w;
            }
            *reinterpret_cast<float4*>(&parts[half * 512 + col]) = acc;
            __syncthreads();
            if (t < 128) {
                int c2 = t * 4;
                float4 p0 = *reinterpret_cast<const float4*>(&parts[c2]);
                float4 p1 = *reinterpret_cast<const float4*>(&parts[512 + c2]);
                float4 cx = make_float4(p0.x + p1.x, p0.y + p1.y, p0.z + p1.z, p0.w + p1.w);
                *reinterpret_cast<float4*>(&g_xec[(size_t)b * 1024 + 512 + c2]) = cx;
                *reinterpret_cast<float4*>(&g_ctxbuf[(size_t)b * 512 + c2]) = cx;
            }
            __syncthreads();
        }
        gbar();

        // ---- cdn ----
        if (blk < 128) {
            gemm4_cdn(g_h1buf[par ^ 1], g_ctxbuf, Wc, AS, b_o2c, u0);
        }
        gbar();

        // ---- logits + argmax + emb feedback ----
        if (blk < 128) {
            int b = blk;
            float* wbest = AS;                 // 8
            int* wvid = (int*)(AS + 8);        // 8
            int* bidx = (int*)(AS + 16);
            float h[16];
#pragma unroll
            for (int jj = 0; jj < 16; jj++)
                h[jj] = __ldcg(&g_hid[(size_t)b * 512 + l + jj * 32]);
            float best = -3.4e38f;
            int bv = 0;
            float* lo = out_logits + ((size_t)b * TDEC + s) * VOCAB;
            for (int v = w; v < VOCAB; v += 8) {
                float sv = 0.f;
#pragma unroll
                for (int jj = 0; jj < 16; jj++)
                    sv += h[jj] * emb[(size_t)v * 512 + l + jj * 32];
#pragma unroll
                for (int o = 16; o > 0; o >>= 1) sv += __shfl_xor_sync(0xffffffffu, sv, o);
                if (l == 0) {
                    sv += b_cp[v];
                    lo[v] = sv;
                    if (sv > best) { best = sv; bv = v; }
                }
            }
            if (l == 0) { wbest[w] = best; wvid[w] = bv; }
            __syncthreads();
            if (t == 0) {
                float bb = wbest[0]; int bi = wvid[0];
                for (int i = 1; i < 8; i++) {
                    if (wbest[i] > bb || (wbest[i] == bb && wvid[i] < bi)) {
                        bb = wbest[i]; bi = wvid[i];
                    }
                }
                *bidx = bi;
            }
            __syncthreads();
            int sym = *bidx;
            for (int u = t; u < 512; u += 256)
                g_xec[(size_t)b * 1024 + u] = emb[(size_t)sym * 512 + u];
            __syncthreads();
        }
        gbar();
    }
}

// ---------------- launch ----------------
extern "C" void kernel_launch(void* const* d_in, const int* in_sizes, int n_in,
                              void* d_out, int out_size) {
    const float* enc    = (const float*)d_in[0];
    const float* emb    = (const float*)d_in[1];
    const float* w_ih0  = (const float*)d_in[2];
    const float* w_hh0  = (const float*)d_in[3];
    const float* b_ih0  = (const float*)d_in[4];
    const float* b_hh0  = (const float*)d_in[5];
    const float* w_ih1  = (const float*)d_in[6];
    const float* w_hh1  = (const float*)d_in[7];
    const float* b_ih1  = (const float*)d_in[8];
    const float* b_hh1  = (const float*)d_in[9];
    const float* wk     = (const float*)d_in[10];
    const float* wv     = (const float*)d_in[11];
    const float* w_o2c  = (const float*)d_in[12];
    const float* b_o2c  = (const float*)d_in[13];
    const float* b_cp   = (const float*)d_in[14];
    float* out = (float*)d_out;
    float* out_logits = out;
    float* out_attn = out + (size_t)BATCH * TDEC * VOCAB;

    cudaFuncSetAttribute(decoder_kernel,
                         cudaFuncAttributeMaxDynamicSharedMemorySize, SMEM_BYTES);

    init_kernel<<<256, 256>>>(emb);
    kv_gemm_kernel<<<dim3(1000, 8, 2), 256>>>(enc, wk, wv);
    decoder_kernel<<<NBLK, NTHR, SMEM_BYTES>>>(emb,
                                   w_ih0, w_hh0, b_ih0, b_hh0,
                                   w_ih1, w_hh1, b_ih1, b_hh1,
                                   w_o2c, b_o2c, b_cp,
                                   out_logits, out_attn);
}